// round 3
// baseline (speedup 1.0000x reference)
#include <cuda_runtime.h>
#include <math.h>

#define BB 2
#define TT 2048
#define NH 16
#define HD 64
#define DD 1024
#define D3 3072
#define BT 4096   // BB*TT

// Scratch (no allocations allowed)
__device__ float g_qkv[(size_t)BT * D3];   // 50 MB
__device__ float g_q  [(size_t)BT * DD];   // 16.8 MB
__device__ float g_ctx[(size_t)BT * DD];   // 16.8 MB

// ---------------------------------------------------------------------------
// SGEMM: C[M,N] = A[M,K] @ B[K,N] + bias[N]
// 128x128 block, BK=8, 256 threads, 8x8 micro-tile. M,N,K multiples of 128/8.
// ---------------------------------------------------------------------------
__global__ __launch_bounds__(256) void sgemm_bias(
    const float* __restrict__ A, const float* __restrict__ Bm,
    const float* __restrict__ bias, float* __restrict__ C,
    int M, int N, int K)
{
    __shared__ float As[8][128];
    __shared__ float Bs[8][128];
    const int tid  = threadIdx.x;
    const int brow = blockIdx.y, bcol = blockIdx.x;
    const float* Ab = A + (size_t)brow * 128 * K;
    const float* Bb = Bm + (size_t)bcol * 128;

    float acc[8][8];
#pragma unroll
    for (int i = 0; i < 8; i++)
#pragma unroll
        for (int j = 0; j < 8; j++) acc[i][j] = 0.f;

    const int a_row = tid >> 1;          // 0..127
    const int a_col = (tid & 1) * 4;     // 0 or 4
    const int b_row = tid >> 5;          // 0..7
    const int b_col = (tid & 31) * 4;    // 0..124
    const int ty = tid >> 4, tx = tid & 15;

    for (int k0 = 0; k0 < K; k0 += 8) {
        float4 av = *(const float4*)(Ab + (size_t)a_row * K + k0 + a_col);
        As[a_col + 0][a_row] = av.x;
        As[a_col + 1][a_row] = av.y;
        As[a_col + 2][a_row] = av.z;
        As[a_col + 3][a_row] = av.w;
        float4 bv = *(const float4*)(Bb + (size_t)(k0 + b_row) * N + b_col);
        *(float4*)&Bs[b_row][b_col] = bv;
        __syncthreads();
#pragma unroll
        for (int k = 0; k < 8; k++) {
            float4 a0 = *(const float4*)&As[k][ty * 8];
            float4 a1 = *(const float4*)&As[k][ty * 8 + 4];
            float4 b0 = *(const float4*)&Bs[k][tx * 8];
            float4 b1 = *(const float4*)&Bs[k][tx * 8 + 4];
            float af[8] = {a0.x, a0.y, a0.z, a0.w, a1.x, a1.y, a1.z, a1.w};
            float bf[8] = {b0.x, b0.y, b0.z, b0.w, b1.x, b1.y, b1.z, b1.w};
#pragma unroll
            for (int i = 0; i < 8; i++)
#pragma unroll
                for (int j = 0; j < 8; j++)
                    acc[i][j] = fmaf(af[i], bf[j], acc[i][j]);
        }
        __syncthreads();
    }

    const float* bptr = bias + (size_t)bcol * 128 + tx * 8;
    float bb[8];
#pragma unroll
    for (int j = 0; j < 8; j++) bb[j] = bptr[j];
#pragma unroll
    for (int i = 0; i < 8; i++) {
        size_t row = (size_t)brow * 128 + ty * 8 + i;
        float* crow = C + row * N + (size_t)bcol * 128 + tx * 8;
        float4 o0, o1;
        o0.x = acc[i][0] + bb[0]; o0.y = acc[i][1] + bb[1];
        o0.z = acc[i][2] + bb[2]; o0.w = acc[i][3] + bb[3];
        o1.x = acc[i][4] + bb[4]; o1.y = acc[i][5] + bb[5];
        o1.z = acc[i][6] + bb[6]; o1.w = acc[i][7] + bb[7];
        *(float4*)crow       = o0;
        *(float4*)(crow + 4) = o1;
    }
}

// ---------------------------------------------------------------------------
// RoPE + scatter: qkv[B,T,3D] -> q scratch [B,T,D], k/v -> cache [B,2,T,D]
// ---------------------------------------------------------------------------
__global__ __launch_bounds__(256) void rope_scatter(
    const float* __restrict__ qkv, float* __restrict__ qout,
    float* __restrict__ cache, const int* __restrict__ offp)
{
    int idx = blockIdx.x * blockDim.x + threadIdx.x;   // BB*TT*NH*32 = 2^21
    int i = idx & 31;
    int h = (idx >> 5) & 15;
    int t = (idx >> 9) & (TT - 1);
    int b = idx >> 20;
    int off = offp ? offp[0] : 0;

    // inv_freq = 10000^(-2i/64) = exp2(-(2i/64) * log2(10000))
    float inv_freq = exp2f(-(float)(2 * i) * (0.015625f * 13.287712379549449f));
    float ang = (float)(t + off) * inv_freq;
    float s, c;
    sincosf(ang, &s, &c);

    size_t base = ((size_t)(b * TT + t)) * D3 + h * HD + 2 * i;
    // Q
    float q1 = qkv[base], q2 = qkv[base + 1];
    size_t qo = ((size_t)(b * TT + t)) * DD + h * HD + 2 * i;
    qout[qo]     = q1 * c - q2 * s;
    qout[qo + 1] = q1 * s + q2 * c;
    // K -> cache[b,0]
    float k1 = qkv[base + DD], k2 = qkv[base + DD + 1];
    size_t ko = ((size_t)((b * 2 + 0) * TT + t)) * DD + h * HD + 2 * i;
    cache[ko]     = k1 * c - k2 * s;
    cache[ko + 1] = k1 * s + k2 * c;
    // V -> cache[b,1] (no rope)
    size_t vo = ((size_t)((b * 2 + 1) * TT + t)) * DD + h * HD + 2 * i;
    cache[vo]     = qkv[base + 2 * DD];
    cache[vo + 1] = qkv[base + 2 * DD + 1];
}

// ---------------------------------------------------------------------------
// Flash attention fp32, causal. BM=BN=64, hd=64, 256 threads.
// grid = (T/64, B*H). Q and K stored TRANSPOSED in smem (dim-major) so the
// S GEMM reads both operands as LDS.128 (broadcast / conflict-free).
// ---------------------------------------------------------------------------
#define ATT_SMEM_FLOATS (4 * 64 * 64 + 3 * 64)
__global__ __launch_bounds__(256) void attn_kernel(
    const float* __restrict__ q, const float* __restrict__ cache,
    float* __restrict__ ctx)
{
    extern __shared__ float smem[];
    float* Qts = smem;                 // [d][r] 64x64
    float* Kts = smem + 4096;          // [d][c] 64x64
    float* Vs  = smem + 8192;          // [k][d] 64x64
    float* Ss  = smem + 12288;         // [r][c] 64x64
    float* mrow = smem + 16384;        // 64
    float* lrow = mrow + 64;           // 64
    float* arow = lrow + 64;           // 64

    const int mblk = blockIdx.x;
    const int bh   = blockIdx.y;
    const int b = bh >> 4, h = bh & 15;
    const int tid = threadIdx.x;
    const int tr = tid >> 4, tc = tid & 15;

    const float* qbase = q + ((size_t)(b * TT)) * DD + h * HD;
    const float* kbase = cache + ((size_t)((b * 2 + 0) * TT)) * DD + h * HD;
    const float* vbase = cache + ((size_t)((b * 2 + 1) * TT)) * DD + h * HD;

    // Load Q tile transposed
    for (int it = tid; it < 64 * 16; it += 256) {
        int r = it >> 4, c4 = (it & 15) * 4;
        float4 v = *(const float4*)(qbase + (size_t)(mblk * 64 + r) * DD + c4);
        Qts[(c4 + 0) * 64 + r] = v.x;
        Qts[(c4 + 1) * 64 + r] = v.y;
        Qts[(c4 + 2) * 64 + r] = v.z;
        Qts[(c4 + 3) * 64 + r] = v.w;
    }
    if (tid < 64) { mrow[tid] = -INFINITY; lrow[tid] = 0.f; }

    float o[4][4];
#pragma unroll
    for (int i = 0; i < 4; i++)
#pragma unroll
        for (int j = 0; j < 4; j++) o[i][j] = 0.f;

    for (int kb = 0; kb <= mblk; kb++) {
        __syncthreads();   // protect K/V/S reuse + first-iter Q/m/l init
        // Load K (transposed) and V tiles
        for (int it = tid; it < 64 * 16; it += 256) {
            int r = it >> 4, c4 = (it & 15) * 4;
            float4 kv = *(const float4*)(kbase + (size_t)(kb * 64 + r) * DD + c4);
            Kts[(c4 + 0) * 64 + r] = kv.x;
            Kts[(c4 + 1) * 64 + r] = kv.y;
            Kts[(c4 + 2) * 64 + r] = kv.z;
            Kts[(c4 + 3) * 64 + r] = kv.w;
            *(float4*)&Vs[r * 64 + c4] =
                *(const float4*)(vbase + (size_t)(kb * 64 + r) * DD + c4);
        }
        __syncthreads();

        // S = scale * Q K^T   (4x4 per thread)
        float s4[4][4];
#pragma unroll
        for (int i = 0; i < 4; i++)
#pragma unroll
            for (int j = 0; j < 4; j++) s4[i][j] = 0.f;
#pragma unroll 8
        for (int d = 0; d < 64; d++) {
            float4 aq = *(const float4*)&Qts[d * 64 + tr * 4];
            float4 bk = *(const float4*)&Kts[d * 64 + tc * 4];
            float af[4] = {aq.x, aq.y, aq.z, aq.w};
            float bf[4] = {bk.x, bk.y, bk.z, bk.w};
#pragma unroll
            for (int i = 0; i < 4; i++)
#pragma unroll
                for (int j = 0; j < 4; j++)
                    s4[i][j] = fmaf(af[i], bf[j], s4[i][j]);
        }
        const float scale = 0.125f;   // 1/sqrt(64)
        bool diag = (kb == mblk);
#pragma unroll
        for (int i = 0; i < 4; i++) {
            int qr = mblk * 64 + tr * 4 + i;
            float4 sv;
            float* sp = (float*)&sv;
#pragma unroll
            for (int j = 0; j < 4; j++) {
                int kc = kb * 64 + tc * 4 + j;
                float v = s4[i][j] * scale;
                if (diag && kc > qr) v = -1e30f;
                sp[j] = v;
            }
            *(float4*)&Ss[(tr * 4 + i) * 64 + tc * 4] = sv;
        }
        __syncthreads();

        // Online softmax: 4 threads per row
        {
            int row = tid >> 2, sub = tid & 3;
            float* srow = &Ss[row * 64 + sub * 16];
            float mx = -1e30f;
#pragma unroll
            for (int cc = 0; cc < 16; cc++) mx = fmaxf(mx, srow[cc]);
            mx = fmaxf(mx, __shfl_xor_sync(0xffffffffu, mx, 1));
            mx = fmaxf(mx, __shfl_xor_sync(0xffffffffu, mx, 2));
            float mold = mrow[row];
            float mnew = fmaxf(mold, mx);
            float sum = 0.f;
#pragma unroll
            for (int cc = 0; cc < 16; cc++) {
                float e = expf(srow[cc] - mnew);
                srow[cc] = e;
                sum += e;
            }
            sum += __shfl_xor_sync(0xffffffffu, sum, 1);
            sum += __shfl_xor_sync(0xffffffffu, sum, 2);
            if (sub == 0) {
                float alpha = expf(mold - mnew);   // 0 when mold=-inf
                arow[row] = alpha;
                mrow[row] = mnew;
                lrow[row] = lrow[row] * alpha + sum;
            }
        }
        __syncthreads();

        // O = O*alpha + P @ V
#pragma unroll
        for (int i = 0; i < 4; i++) {
            float al = arow[tr * 4 + i];
#pragma unroll
            for (int j = 0; j < 4; j++) o[i][j] *= al;
        }
#pragma unroll 8
        for (int kk = 0; kk < 64; kk++) {
            float4 vv = *(const float4*)&Vs[kk * 64 + tc * 4];
#pragma unroll
            for (int i = 0; i < 4; i++) {
                float p = Ss[(tr * 4 + i) * 64 + kk];
                o[i][0] = fmaf(p, vv.x, o[i][0]);
                o[i][1] = fmaf(p, vv.y, o[i][1]);
                o[i][2] = fmaf(p, vv.z, o[i][2]);
                o[i][3] = fmaf(p, vv.w, o[i][3]);
            }
        }
    }

    // Finalize: ctx[b, t, h*64 + d] = O / l
#pragma unroll
    for (int i = 0; i < 4; i++) {
        float inv = 1.f / lrow[tr * 4 + i];
        size_t row = (size_t)(b * TT + mblk * 64 + tr * 4 + i);
        float4 ov;
        ov.x = o[i][0] * inv; ov.y = o[i][1] * inv;
        ov.z = o[i][2] * inv; ov.w = o[i][3] * inv;
        *(float4*)(ctx + row * DD + h * HD + tc * 4) = ov;
    }
}

// ---------------------------------------------------------------------------
extern "C" void kernel_launch(void* const* d_in, const int* in_sizes, int n_in,
                              void* d_out, int out_size)
{
    const float* x    = (const float*)d_in[0];
    const float* Wqkv = (const float*)d_in[1];
    const float* bqkv = (const float*)d_in[2];
    const float* Wout = (const float*)d_in[3];
    const float* bout = (const float*)d_in[4];
    const int*   offp = (n_in > 5) ? (const int*)d_in[5] : nullptr;

    float* out   = (float*)d_out;
    float* cache = out + (size_t)BT * DD;   // new_cache region

    float *qkv, *qbuf, *ctx;
    cudaGetSymbolAddress((void**)&qkv,  g_qkv);
    cudaGetSymbolAddress((void**)&qbuf, g_q);
    cudaGetSymbolAddress((void**)&ctx,  g_ctx);

    // 1) QKV projection
    sgemm_bias<<<dim3(D3 / 128, BT / 128), 256>>>(x, Wqkv, bqkv, qkv, BT, D3, DD);

    // 2) RoPE + scatter q / k / v
    rope_scatter<<<(BB * TT * NH * 32) / 256, 256>>>(qkv, qbuf, cache, offp);

    // 3) Causal flash attention
    size_t att_smem = ATT_SMEM_FLOATS * sizeof(float);
    cudaFuncSetAttribute(attn_kernel, cudaFuncAttributeMaxDynamicSharedMemorySize,
                         (int)att_smem);
    attn_kernel<<<dim3(TT / 64, BB * NH), 256, att_smem>>>(qbuf, cache, ctx);

    // 4) Output projection
    sgemm_bias<<<dim3(DD / 128, BT / 128), 256>>>(ctx, Wout, bout, out, BT, DD, DD);
}

// round 5
// speedup vs baseline: 1.3451x; 1.3451x over previous
#include <cuda_runtime.h>
#include <cuda_bf16.h>
#include <math.h>
#include <stdint.h>

#define BB 2
#define TT 2048
#define NH 16
#define HD 64
#define DD 1024
#define D3 3072
#define BT 4096   // BB*TT

// ---------------------------------------------------------------------------
// Scratch (no allocations allowed)
// ---------------------------------------------------------------------------
__device__ float g_qkv[(size_t)BT * D3];
__device__ float g_q  [(size_t)BT * DD];
__device__ float g_ctx[(size_t)BT * DD];
__device__ __nv_bfloat16 g_x_hi [(size_t)BT * DD];
__device__ __nv_bfloat16 g_x_lo [(size_t)BT * DD];
__device__ __nv_bfloat16 g_c_hi [(size_t)BT * DD];
__device__ __nv_bfloat16 g_c_lo [(size_t)BT * DD];
__device__ __nv_bfloat16 g_wq_hi[(size_t)D3 * DD];   // Wqkv^T
__device__ __nv_bfloat16 g_wq_lo[(size_t)D3 * DD];
__device__ __nv_bfloat16 g_wo_hi[(size_t)DD * DD];   // Wout^T
__device__ __nv_bfloat16 g_wo_lo[(size_t)DD * DD];

// ---------------------------------------------------------------------------
__device__ __forceinline__ uint32_t smem_u32(const void* p) {
    uint32_t a;
    asm("{ .reg .u64 t; cvta.to.shared.u64 t, %1; cvt.u32.u64 %0, t; }"
        : "=r"(a) : "l"(p));
    return a;
}
__device__ __forceinline__ void bf16_split(float v, __nv_bfloat16& h, __nv_bfloat16& l) {
    h = __float2bfloat16_rn(v);
    l = __float2bfloat16_rn(v - __bfloat162float(h));
}
__device__ __forceinline__ void cp16(uint32_t dst, const void* src) {
    asm volatile("cp.async.ca.shared.global [%0], [%1], 16;" :: "r"(dst), "l"(src));
}
__device__ __forceinline__ void cp_commit() {
    asm volatile("cp.async.commit_group;" ::: "memory");
}
__device__ __forceinline__ void cp_wait0() {
    asm volatile("cp.async.wait_group 0;" ::: "memory");
}
__device__ __forceinline__ void cp_wait1() {
    asm volatile("cp.async.wait_group 1;" ::: "memory");
}
__device__ __forceinline__ void ldm_x4(uint32_t* r, uint32_t addr) {
    asm volatile("ldmatrix.sync.aligned.m8n8.x4.shared.b16 {%0,%1,%2,%3}, [%4];"
                 : "=r"(r[0]), "=r"(r[1]), "=r"(r[2]), "=r"(r[3]) : "r"(addr));
}
__device__ __forceinline__ void ldm_x2(uint32_t* r, uint32_t addr) {
    asm volatile("ldmatrix.sync.aligned.m8n8.x2.shared.b16 {%0,%1}, [%2];"
                 : "=r"(r[0]), "=r"(r[1]) : "r"(addr));
}
__device__ __forceinline__ void mma16816(float* c, const uint32_t* a, const uint32_t* b) {
    asm volatile(
        "mma.sync.aligned.m16n8k16.row.col.f32.bf16.bf16.f32 "
        "{%0,%1,%2,%3}, {%4,%5,%6,%7}, {%8,%9}, {%0,%1,%2,%3};"
        : "+f"(c[0]), "+f"(c[1]), "+f"(c[2]), "+f"(c[3])
        : "r"(a[0]), "r"(a[1]), "r"(a[2]), "r"(a[3]), "r"(b[0]), "r"(b[1]));
}

// ---------------------------------------------------------------------------
// Elementwise fp32 -> bf16 hi/lo split
// ---------------------------------------------------------------------------
__global__ __launch_bounds__(256) void split_bf16(
    const float* __restrict__ src, __nv_bfloat16* __restrict__ hi,
    __nv_bfloat16* __restrict__ lo, int n4)
{
    int i = blockIdx.x * blockDim.x + threadIdx.x;
    if (i >= n4) return;
    float4 v = *(const float4*)(src + (size_t)i * 4);
    __nv_bfloat16 h[4], l[4];
    bf16_split(v.x, h[0], l[0]);
    bf16_split(v.y, h[1], l[1]);
    bf16_split(v.z, h[2], l[2]);
    bf16_split(v.w, h[3], l[3]);
    *(uint64_t*)(hi + (size_t)i * 4) = *(uint64_t*)h;
    *(uint64_t*)(lo + (size_t)i * 4) = *(uint64_t*)l;
}

// ---------------------------------------------------------------------------
// Transpose + bf16 split: W[K][N] -> Thi/Tlo[N][K] bf16
// ---------------------------------------------------------------------------
__global__ __launch_bounds__(256) void transpose_split(
    const float* __restrict__ W, __nv_bfloat16* __restrict__ Thi,
    __nv_bfloat16* __restrict__ Tlo, int K, int N)
{
    __shared__ float t[32][33];
    const int nb = blockIdx.x * 32, kb = blockIdx.y * 32;
    const int tx = threadIdx.x & 31, ty0 = threadIdx.x >> 5;
#pragma unroll
    for (int i = 0; i < 4; i++) {
        int row = ty0 + i * 8;
        t[row][tx] = W[(size_t)(kb + row) * N + nb + tx];
    }
    __syncthreads();
#pragma unroll
    for (int i = 0; i < 4; i++) {
        int row = ty0 + i * 8;
        float v = t[tx][row];
        __nv_bfloat16 h, l;
        bf16_split(v, h, l);
        size_t o = (size_t)(nb + row) * K + kb + tx;
        Thi[o] = h;
        Tlo[o] = l;
    }
}

// ---------------------------------------------------------------------------
// bf16-split GEMM via mma.sync: C[M,N] = A[M,K] @ Bt[N,K]^T + bias
// A,Bt pre-split bf16 hi/lo. 128x128 CTA tile, BK=32, double-buffered cp.async.
// 8 warps, warp tile 64(M)x32(N). 3-term split: hh + hl + lh.
// ---------------------------------------------------------------------------
#define GSMEM (2 * 32768)

__global__ __launch_bounds__(256) void gemm_bf16(
    const __nv_bfloat16* __restrict__ Ahi, const __nv_bfloat16* __restrict__ Alo,
    const __nv_bfloat16* __restrict__ Bhi, const __nv_bfloat16* __restrict__ Blo,
    const float* __restrict__ bias, float* __restrict__ C,
    int M, int N, int K)
{
    extern __shared__ char sm[];
    const uint32_t sB = smem_u32(sm);
    const int tid = threadIdx.x, wid = tid >> 5, lane = tid & 31;
    const int bn = blockIdx.x, bm = blockIdx.y;
    const int wm = wid & 1, wn = wid >> 1;          // 2 x 4 warp grid
    const int NC = K >> 5;

    const __nv_bfloat16* gbase[4];
    gbase[0] = Ahi + (size_t)bm * 128 * K;
    gbase[1] = Alo + (size_t)bm * 128 * K;
    gbase[2] = Bhi + (size_t)bn * 128 * K;
    gbase[3] = Blo + (size_t)bn * 128 * K;

    // loader: tile rows 128 x 32 bf16 (64B) each, 4 chunks of 16B, XOR swizzle
    auto load_chunk = [&](int c, int s) {
#pragma unroll
        for (int t = 0; t < 8; t++) {
            int id = tid + t * 256;           // 0..2047
            int tile = id >> 9;               // 0..3
            int rem = id & 511;
            int row = rem >> 2, ch = rem & 3;
            const __nv_bfloat16* src = gbase[tile] + (size_t)row * K + c * 32 + ch * 8;
            uint32_t dst = sB + s * 32768 + tile * 8192 + row * 64 +
                           ((ch ^ (row & 3)) << 4);
            cp16(dst, src);
        }
    };

    float acc[4][4][4];
#pragma unroll
    for (int i = 0; i < 4; i++)
#pragma unroll
        for (int j = 0; j < 4; j++)
#pragma unroll
            for (int k = 0; k < 4; k++) acc[i][j][k] = 0.f;

    const int l15 = lane & 15, lhi = lane >> 4;
    const int aRowPar = l15 & 3;
    const int bRow7 = lane & 7, bK = (lane >> 3) & 1, bRowPar = lane & 3;

    load_chunk(0, 0);
    cp_commit();

    for (int c = 0; c < NC; c++) {
        const int s = c & 1;
        if (c + 1 < NC) {
            load_chunk(c + 1, s ^ 1);
            cp_commit();
            cp_wait1();
        } else {
            cp_wait0();
        }
        __syncthreads();

        const uint32_t base = sB + s * 32768;
        const uint32_t aHiT = base, aLoT = base + 8192;
        const uint32_t bHiT = base + 16384, bLoT = base + 24576;

#pragma unroll
        for (int ks = 0; ks < 2; ks++) {
            const int ks2 = ks * 2;
            uint32_t aOff[4], bOff[4];
#pragma unroll
            for (int mt = 0; mt < 4; mt++) {
                int row = wm * 64 + mt * 16 + l15;
                aOff[mt] = row * 64 + (((ks2 + lhi) ^ aRowPar) << 4);
            }
#pragma unroll
            for (int nt = 0; nt < 4; nt++) {
                int row = wn * 32 + nt * 8 + bRow7;
                bOff[nt] = row * 64 + (((ks2 + bK) ^ bRowPar) << 4);
            }

            uint32_t aF[4][4], bF[4][2], bF2[4][2];
#pragma unroll
            for (int mt = 0; mt < 4; mt++) ldm_x4(aF[mt], aHiT + aOff[mt]);
#pragma unroll
            for (int nt = 0; nt < 4; nt++) ldm_x2(bF[nt], bHiT + bOff[nt]);
            // term hh
#pragma unroll
            for (int mt = 0; mt < 4; mt++)
#pragma unroll
                for (int nt = 0; nt < 4; nt++)
                    mma16816(acc[mt][nt], aF[mt], bF[nt]);
            // term hl
#pragma unroll
            for (int nt = 0; nt < 4; nt++) ldm_x2(bF2[nt], bLoT + bOff[nt]);
#pragma unroll
            for (int mt = 0; mt < 4; mt++)
#pragma unroll
                for (int nt = 0; nt < 4; nt++)
                    mma16816(acc[mt][nt], aF[mt], bF2[nt]);
            // term lh
#pragma unroll
            for (int mt = 0; mt < 4; mt++) ldm_x4(aF[mt], aLoT + aOff[mt]);
#pragma unroll
            for (int mt = 0; mt < 4; mt++)
#pragma unroll
                for (int nt = 0; nt < 4; nt++)
                    mma16816(acc[mt][nt], aF[mt], bF[nt]);
        }
        __syncthreads();
    }

    // Epilogue: direct v2 stores + bias
    const int g = lane >> 2, tg2 = (lane & 3) * 2;
#pragma unroll
    for (int nt = 0; nt < 4; nt++) {
        const int col = bn * 128 + wn * 32 + nt * 8 + tg2;
        const float b0 = bias[col], b1 = bias[col + 1];
#pragma unroll
        for (int mt = 0; mt < 4; mt++) {
            const int r0 = bm * 128 + wm * 64 + mt * 16 + g;
            float2 v0 = make_float2(acc[mt][nt][0] + b0, acc[mt][nt][1] + b1);
            float2 v1 = make_float2(acc[mt][nt][2] + b0, acc[mt][nt][3] + b1);
            *(float2*)(C + (size_t)r0 * N + col) = v0;
            *(float2*)(C + (size_t)(r0 + 8) * N + col) = v1;
        }
    }
}

// ---------------------------------------------------------------------------
// RoPE + scatter: qkv[B,T,3D] -> q scratch [B,T,D], k/v -> cache [B,2,T,D]
// ---------------------------------------------------------------------------
__global__ __launch_bounds__(256) void rope_scatter(
    const float* __restrict__ qkv, float* __restrict__ qout,
    float* __restrict__ cache, const int* __restrict__ offp)
{
    int idx = blockIdx.x * blockDim.x + threadIdx.x;
    int i = idx & 31;
    int h = (idx >> 5) & 15;
    int t = (idx >> 9) & (TT - 1);
    int b = idx >> 20;
    int off = offp ? offp[0] : 0;

    float inv_freq = exp2f(-(float)(2 * i) * (0.015625f * 13.287712379549449f));
    float ang = (float)(t + off) * inv_freq;
    float s, c;
    sincosf(ang, &s, &c);

    size_t base = ((size_t)(b * TT + t)) * D3 + h * HD + 2 * i;
    float q1 = qkv[base], q2 = qkv[base + 1];
    size_t qo = ((size_t)(b * TT + t)) * DD + h * HD + 2 * i;
    qout[qo]     = q1 * c - q2 * s;
    qout[qo + 1] = q1 * s + q2 * c;
    float k1 = qkv[base + DD], k2 = qkv[base + DD + 1];
    size_t ko = ((size_t)((b * 2 + 0) * TT + t)) * DD + h * HD + 2 * i;
    cache[ko]     = k1 * c - k2 * s;
    cache[ko + 1] = k1 * s + k2 * c;
    size_t vo = ((size_t)((b * 2 + 1) * TT + t)) * DD + h * HD + 2 * i;
    cache[vo]     = qkv[base + 2 * DD];
    cache[vo + 1] = qkv[base + 2 * DD + 1];
}

// ---------------------------------------------------------------------------
// Flash attention fp32, causal. BM=BN=64, hd=64, 256 threads.
// ---------------------------------------------------------------------------
#define ATT_SMEM_FLOATS (4 * 64 * 64 + 3 * 64)
__global__ __launch_bounds__(256) void attn_kernel(
    const float* __restrict__ q, const float* __restrict__ cache,
    float* __restrict__ ctx)
{
    extern __shared__ float smf[];
    float* Qts = smf;
    float* Kts = smf + 4096;
    float* Vs  = smf + 8192;
    float* Ss  = smf + 12288;
    float* mrow = smf + 16384;
    float* lrow = mrow + 64;
    float* arow = lrow + 64;

    const int mblk = blockIdx.x;
    const int bh   = blockIdx.y;
    const int b = bh >> 4, h = bh & 15;
    const int tid = threadIdx.x;
    const int tr = tid >> 4, tc = tid & 15;

    const float* qbase = q + ((size_t)(b * TT)) * DD + h * HD;
    const float* kbase = cache + ((size_t)((b * 2 + 0) * TT)) * DD + h * HD;
    const float* vbase = cache + ((size_t)((b * 2 + 1) * TT)) * DD + h * HD;

    for (int it = tid; it < 64 * 16; it += 256) {
        int r = it >> 4, c4 = (it & 15) * 4;
        float4 v = *(const float4*)(qbase + (size_t)(mblk * 64 + r) * DD + c4);
        Qts[(c4 + 0) * 64 + r] = v.x;
        Qts[(c4 + 1) * 64 + r] = v.y;
        Qts[(c4 + 2) * 64 + r] = v.z;
        Qts[(c4 + 3) * 64 + r] = v.w;
    }
    if (tid < 64) { mrow[tid] = -INFINITY; lrow[tid] = 0.f; }

    float o[4][4];
#pragma unroll
    for (int i = 0; i < 4; i++)
#pragma unroll
        for (int j = 0; j < 4; j++) o[i][j] = 0.f;

    for (int kb = 0; kb <= mblk; kb++) {
        __syncthreads();
        for (int it = tid; it < 64 * 16; it += 256) {
            int r = it >> 4, c4 = (it & 15) * 4;
            float4 kv = *(const float4*)(kbase + (size_t)(kb * 64 + r) * DD + c4);
            Kts[(c4 + 0) * 64 + r] = kv.x;
            Kts[(c4 + 1) * 64 + r] = kv.y;
            Kts[(c4 + 2) * 64 + r] = kv.z;
            Kts[(c4 + 3) * 64 + r] = kv.w;
            *(float4*)&Vs[r * 64 + c4] =
                *(const float4*)(vbase + (size_t)(kb * 64 + r) * DD + c4);
        }
        __syncthreads();

        float s4[4][4];
#pragma unroll
        for (int i = 0; i < 4; i++)
#pragma unroll
            for (int j = 0; j < 4; j++) s4[i][j] = 0.f;
#pragma unroll 8
        for (int d = 0; d < 64; d++) {
            float4 aq = *(const float4*)&Qts[d * 64 + tr * 4];
            float4 bk = *(const float4*)&Kts[d * 64 + tc * 4];
            float af[4] = {aq.x, aq.y, aq.z, aq.w};
            float bf[4] = {bk.x, bk.y, bk.z, bk.w};
#pragma unroll
            for (int i = 0; i < 4; i++)
#pragma unroll
                for (int j = 0; j < 4; j++)
                    s4[i][j] = fmaf(af[i], bf[j], s4[i][j]);
        }
        const float scale = 0.125f;
        bool diag = (kb == mblk);
#pragma unroll
        for (int i = 0; i < 4; i++) {
            int qr = mblk * 64 + tr * 4 + i;
            float4 sv;
            float* sp = (float*)&sv;
#pragma unroll
            for (int j = 0; j < 4; j++) {
                int kc = kb * 64 + tc * 4 + j;
                float v = s4[i][j] * scale;
                if (diag && kc > qr) v = -1e30f;
                sp[j] = v;
            }
            *(float4*)&Ss[(tr * 4 + i) * 64 + tc * 4] = sv;
        }
        __syncthreads();

        {
            int row = tid >> 2, sub = tid & 3;
            float* srow = &Ss[row * 64 + sub * 16];
            float mx = -1e30f;
#pragma unroll
            for (int cc = 0; cc < 16; cc++) mx = fmaxf(mx, srow[cc]);
            mx = fmaxf(mx, __shfl_xor_sync(0xffffffffu, mx, 1));
            mx = fmaxf(mx, __shfl_xor_sync(0xffffffffu, mx, 2));
            float mold = mrow[row];
            float mnew = fmaxf(mold, mx);
            float sum = 0.f;
#pragma unroll
            for (int cc = 0; cc < 16; cc++) {
                float e = __expf(srow[cc] - mnew);
                srow[cc] = e;
                sum += e;
            }
            sum += __shfl_xor_sync(0xffffffffu, sum, 1);
            sum += __shfl_xor_sync(0xffffffffu, sum, 2);
            if (sub == 0) {
                float alpha = __expf(mold - mnew);
                if (mold == -INFINITY) alpha = 0.f;
                arow[row] = alpha;
                mrow[row] = mnew;
                lrow[row] = lrow[row] * alpha + sum;
            }
        }
        __syncthreads();

#pragma unroll
        for (int i = 0; i < 4; i++) {
            float al = arow[tr * 4 + i];
#pragma unroll
            for (int j = 0; j < 4; j++) o[i][j] *= al;
        }
#pragma unroll 8
        for (int kk = 0; kk < 64; kk++) {
            float4 vv = *(const float4*)&Vs[kk * 64 + tc * 4];
#pragma unroll
            for (int i = 0; i < 4; i++) {
                float p = Ss[(tr * 4 + i) * 64 + kk];
                o[i][0] = fmaf(p, vv.x, o[i][0]);
                o[i][1] = fmaf(p, vv.y, o[i][1]);
                o[i][2] = fmaf(p, vv.z, o[i][2]);
                o[i][3] = fmaf(p, vv.w, o[i][3]);
            }
        }
    }

#pragma unroll
    for (int i = 0; i < 4; i++) {
        float inv = 1.f / lrow[tr * 4 + i];
        size_t row = (size_t)(b * TT + mblk * 64 + tr * 4 + i);
        float4 ov;
        ov.x = o[i][0] * inv; ov.y = o[i][1] * inv;
        ov.z = o[i][2] * inv; ov.w = o[i][3] * inv;
        *(float4*)(ctx + row * DD + h * HD + tc * 4) = ov;
    }
}

// ---------------------------------------------------------------------------
extern "C" void kernel_launch(void* const* d_in, const int* in_sizes, int n_in,
                              void* d_out, int out_size)
{
    const float* x    = (const float*)d_in[0];
    const float* Wqkv = (const float*)d_in[1];
    const float* bqkv = (const float*)d_in[2];
    const float* Wout = (const float*)d_in[3];
    const float* bout = (const float*)d_in[4];
    const int*   offp = (n_in > 5) ? (const int*)d_in[5] : nullptr;

    float* out   = (float*)d_out;
    float* cache = out + (size_t)BT * DD;

    float *qkv, *qbuf, *ctx;
    __nv_bfloat16 *xh, *xl, *ch, *cl, *wqh, *wql, *woh, *wol;
    cudaGetSymbolAddress((void**)&qkv,  g_qkv);
    cudaGetSymbolAddress((void**)&qbuf, g_q);
    cudaGetSymbolAddress((void**)&ctx,  g_ctx);
    cudaGetSymbolAddress((void**)&xh,   g_x_hi);
    cudaGetSymbolAddress((void**)&xl,   g_x_lo);
    cudaGetSymbolAddress((void**)&ch,   g_c_hi);
    cudaGetSymbolAddress((void**)&cl,   g_c_lo);
    cudaGetSymbolAddress((void**)&wqh,  g_wq_hi);
    cudaGetSymbolAddress((void**)&wql,  g_wq_lo);
    cudaGetSymbolAddress((void**)&woh,  g_wo_hi);
    cudaGetSymbolAddress((void**)&wol,  g_wo_lo);

    cudaFuncSetAttribute(gemm_bf16, cudaFuncAttributeMaxDynamicSharedMemorySize,
                         GSMEM);
    size_t att_smem = ATT_SMEM_FLOATS * sizeof(float);
    cudaFuncSetAttribute(attn_kernel, cudaFuncAttributeMaxDynamicSharedMemorySize,
                         (int)att_smem);

    // 0) splits
    split_bf16<<<(BT * DD / 4) / 256, 256>>>(x, xh, xl, BT * DD / 4);
    transpose_split<<<dim3(D3 / 32, DD / 32), 256>>>(Wqkv, wqh, wql, DD, D3);
    transpose_split<<<dim3(DD / 32, DD / 32), 256>>>(Wout, woh, wol, DD, DD);

    // 1) QKV projection (bf16-split mma.sync)
    gemm_bf16<<<dim3(D3 / 128, BT / 128), 256, GSMEM>>>(
        xh, xl, wqh, wql, bqkv, qkv, BT, D3, DD);

    // 2) RoPE + scatter
    rope_scatter<<<(BB * TT * NH * 32) / 256, 256>>>(qkv, qbuf, cache, offp);

    // 3) Causal flash attention
    attn_kernel<<<dim3(TT / 64, BB * NH), 256, att_smem>>>(qbuf, cache, ctx);

    // 4) Output projection
    split_bf16<<<(BT * DD / 4) / 256, 256>>>(ctx, ch, cl, BT * DD / 4);
    gemm_bf16<<<dim3(DD / 128, BT / 128), 256, GSMEM>>>(
        ch, cl, woh, wol, bout, out, BT, DD, DD);
}

// round 7
// speedup vs baseline: 2.8681x; 2.1322x over previous
#include <cuda_runtime.h>
#include <cuda_bf16.h>
#include <math.h>
#include <stdint.h>

#define BB 2
#define TT 2048
#define NH 16
#define HD 64
#define DD 1024
#define D3 3072
#define BT 4096   // BB*TT

// ---------------------------------------------------------------------------
// Scratch (no allocations allowed)
// ---------------------------------------------------------------------------
__device__ float g_qkv[(size_t)BT * D3];
__device__ float g_q  [(size_t)BT * DD];
__device__ float g_ctx[(size_t)BT * DD];
__device__ __nv_bfloat16 g_x_hi [(size_t)BT * DD];
__device__ __nv_bfloat16 g_x_lo [(size_t)BT * DD];
__device__ __nv_bfloat16 g_c_hi [(size_t)BT * DD];
__device__ __nv_bfloat16 g_c_lo [(size_t)BT * DD];
__device__ __nv_bfloat16 g_wq_hi[(size_t)D3 * DD];   // Wqkv^T
__device__ __nv_bfloat16 g_wq_lo[(size_t)D3 * DD];
__device__ __nv_bfloat16 g_wo_hi[(size_t)DD * DD];   // Wout^T
__device__ __nv_bfloat16 g_wo_lo[(size_t)DD * DD];

// ---------------------------------------------------------------------------
__device__ __forceinline__ uint32_t smem_u32(const void* p) {
    uint32_t a;
    asm("{ .reg .u64 t; cvta.to.shared.u64 t, %1; cvt.u32.u64 %0, t; }"
        : "=r"(a) : "l"(p));
    return a;
}
__device__ __forceinline__ void bf16_split(float v, __nv_bfloat16& h, __nv_bfloat16& l) {
    h = __float2bfloat16_rn(v);
    l = __float2bfloat16_rn(v - __bfloat162float(h));
}
__device__ __forceinline__ void cp16(uint32_t dst, const void* src) {
    asm volatile("cp.async.ca.shared.global [%0], [%1], 16;" :: "r"(dst), "l"(src));
}
__device__ __forceinline__ void cp_commit() {
    asm volatile("cp.async.commit_group;" ::: "memory");
}
__device__ __forceinline__ void cp_wait0() {
    asm volatile("cp.async.wait_group 0;" ::: "memory");
}
__device__ __forceinline__ void cp_wait1() {
    asm volatile("cp.async.wait_group 1;" ::: "memory");
}
__device__ __forceinline__ void ldm_x4(uint32_t* r, uint32_t addr) {
    asm volatile("ldmatrix.sync.aligned.m8n8.x4.shared.b16 {%0,%1,%2,%3}, [%4];"
                 : "=r"(r[0]), "=r"(r[1]), "=r"(r[2]), "=r"(r[3]) : "r"(addr));
}
__device__ __forceinline__ void ldm_x2(uint32_t* r, uint32_t addr) {
    asm volatile("ldmatrix.sync.aligned.m8n8.x2.shared.b16 {%0,%1}, [%2];"
                 : "=r"(r[0]), "=r"(r[1]) : "r"(addr));
}
__device__ __forceinline__ void ldm_x2t(uint32_t* r, uint32_t addr) {
    asm volatile("ldmatrix.sync.aligned.m8n8.x2.trans.shared.b16 {%0,%1}, [%2];"
                 : "=r"(r[0]), "=r"(r[1]) : "r"(addr));
}
__device__ __forceinline__ void mma16816(float* c, const uint32_t* a, const uint32_t* b) {
    asm volatile(
        "mma.sync.aligned.m16n8k16.row.col.f32.bf16.bf16.f32 "
        "{%0,%1,%2,%3}, {%4,%5,%6,%7}, {%8,%9}, {%0,%1,%2,%3};"
        : "+f"(c[0]), "+f"(c[1]), "+f"(c[2]), "+f"(c[3])
        : "r"(a[0]), "r"(a[1]), "r"(a[2]), "r"(a[3]), "r"(b[0]), "r"(b[1]));
}
// pack(lo, hi): low 16 bits = bf16(lo), high = bf16(hi)
__device__ __forceinline__ uint32_t pack_bf16(float lo, float hi) {
    uint32_t r;
    asm("cvt.rn.bf16x2.f32 %0, %1, %2;" : "=r"(r) : "f"(hi), "f"(lo));
    return r;
}
// split pair (a,b) into hi bf16x2 + residual-lo bf16x2 (a in low half)
__device__ __forceinline__ void split2(float a, float b, uint32_t& hi, uint32_t& lo) {
    hi = pack_bf16(a, b);
    float ra = a - __uint_as_float(hi << 16);
    float rb = b - __uint_as_float(hi & 0xffff0000u);
    lo = pack_bf16(ra, rb);
}

// ---------------------------------------------------------------------------
// Elementwise fp32 -> bf16 hi/lo split
// ---------------------------------------------------------------------------
__global__ __launch_bounds__(256) void split_bf16(
    const float* __restrict__ src, __nv_bfloat16* __restrict__ hi,
    __nv_bfloat16* __restrict__ lo, int n4)
{
    int i = blockIdx.x * blockDim.x + threadIdx.x;
    if (i >= n4) return;
    float4 v = *(const float4*)(src + (size_t)i * 4);
    __nv_bfloat16 h[4], l[4];
    bf16_split(v.x, h[0], l[0]);
    bf16_split(v.y, h[1], l[1]);
    bf16_split(v.z, h[2], l[2]);
    bf16_split(v.w, h[3], l[3]);
    *(uint64_t*)(hi + (size_t)i * 4) = *(uint64_t*)h;
    *(uint64_t*)(lo + (size_t)i * 4) = *(uint64_t*)l;
}

// ---------------------------------------------------------------------------
// Transpose + bf16 split: W[K][N] -> Thi/Tlo[N][K] bf16
// ---------------------------------------------------------------------------
__global__ __launch_bounds__(256) void transpose_split(
    const float* __restrict__ W, __nv_bfloat16* __restrict__ Thi,
    __nv_bfloat16* __restrict__ Tlo, int K, int N)
{
    __shared__ float t[32][33];
    const int nb = blockIdx.x * 32, kb = blockIdx.y * 32;
    const int tx = threadIdx.x & 31, ty0 = threadIdx.x >> 5;
#pragma unroll
    for (int i = 0; i < 4; i++) {
        int row = ty0 + i * 8;
        t[row][tx] = W[(size_t)(kb + row) * N + nb + tx];
    }
    __syncthreads();
#pragma unroll
    for (int i = 0; i < 4; i++) {
        int row = ty0 + i * 8;
        float v = t[tx][row];
        __nv_bfloat16 h, l;
        bf16_split(v, h, l);
        size_t o = (size_t)(nb + row) * K + kb + tx;
        Thi[o] = h;
        Tlo[o] = l;
    }
}

// ---------------------------------------------------------------------------
// bf16-split GEMM via mma.sync (unchanged except launch_bounds 2 CTAs/SM)
// ---------------------------------------------------------------------------
#define GSMEM (2 * 32768)

__global__ __launch_bounds__(256, 2) void gemm_bf16(
    const __nv_bfloat16* __restrict__ Ahi, const __nv_bfloat16* __restrict__ Alo,
    const __nv_bfloat16* __restrict__ Bhi, const __nv_bfloat16* __restrict__ Blo,
    const float* __restrict__ bias, float* __restrict__ C,
    int M, int N, int K)
{
    extern __shared__ char sm[];
    const uint32_t sB = smem_u32(sm);
    const int tid = threadIdx.x, wid = tid >> 5, lane = tid & 31;
    const int bn = blockIdx.x, bm = blockIdx.y;
    const int wm = wid & 1, wn = wid >> 1;
    const int NC = K >> 5;

    const __nv_bfloat16* gbase[4];
    gbase[0] = Ahi + (size_t)bm * 128 * K;
    gbase[1] = Alo + (size_t)bm * 128 * K;
    gbase[2] = Bhi + (size_t)bn * 128 * K;
    gbase[3] = Blo + (size_t)bn * 128 * K;

    auto load_chunk = [&](int c, int s) {
#pragma unroll
        for (int t = 0; t < 8; t++) {
            int id = tid + t * 256;
            int tile = id >> 9;
            int rem = id & 511;
            int row = rem >> 2, ch = rem & 3;
            const __nv_bfloat16* src = gbase[tile] + (size_t)row * K + c * 32 + ch * 8;
            uint32_t dst = sB + s * 32768 + tile * 8192 + row * 64 +
                           ((ch ^ (row & 3)) << 4);
            cp16(dst, src);
        }
    };

    float acc[4][4][4];
#pragma unroll
    for (int i = 0; i < 4; i++)
#pragma unroll
        for (int j = 0; j < 4; j++)
#pragma unroll
            for (int k = 0; k < 4; k++) acc[i][j][k] = 0.f;

    const int l15 = lane & 15, lhi = lane >> 4;
    const int aRowPar = l15 & 3;
    const int bRow7 = lane & 7, bK = (lane >> 3) & 1, bRowPar = lane & 3;

    load_chunk(0, 0);
    cp_commit();

    for (int c = 0; c < NC; c++) {
        const int s = c & 1;
        if (c + 1 < NC) {
            load_chunk(c + 1, s ^ 1);
            cp_commit();
            cp_wait1();
        } else {
            cp_wait0();
        }
        __syncthreads();

        const uint32_t base = sB + s * 32768;
        const uint32_t aHiT = base, aLoT = base + 8192;
        const uint32_t bHiT = base + 16384, bLoT = base + 24576;

#pragma unroll
        for (int ks = 0; ks < 2; ks++) {
            const int ks2 = ks * 2;
            uint32_t aOff[4], bOff[4];
#pragma unroll
            for (int mt = 0; mt < 4; mt++) {
                int row = wm * 64 + mt * 16 + l15;
                aOff[mt] = row * 64 + (((ks2 + lhi) ^ aRowPar) << 4);
            }
#pragma unroll
            for (int nt = 0; nt < 4; nt++) {
                int row = wn * 32 + nt * 8 + bRow7;
                bOff[nt] = row * 64 + (((ks2 + bK) ^ bRowPar) << 4);
            }

            uint32_t aF[4][4], bF[4][2], bF2[4][2];
#pragma unroll
            for (int mt = 0; mt < 4; mt++) ldm_x4(aF[mt], aHiT + aOff[mt]);
#pragma unroll
            for (int nt = 0; nt < 4; nt++) ldm_x2(bF[nt], bHiT + bOff[nt]);
#pragma unroll
            for (int mt = 0; mt < 4; mt++)
#pragma unroll
                for (int nt = 0; nt < 4; nt++)
                    mma16816(acc[mt][nt], aF[mt], bF[nt]);
#pragma unroll
            for (int nt = 0; nt < 4; nt++) ldm_x2(bF2[nt], bLoT + bOff[nt]);
#pragma unroll
            for (int mt = 0; mt < 4; mt++)
#pragma unroll
                for (int nt = 0; nt < 4; nt++)
                    mma16816(acc[mt][nt], aF[mt], bF2[nt]);
#pragma unroll
            for (int mt = 0; mt < 4; mt++) ldm_x4(aF[mt], aLoT + aOff[mt]);
#pragma unroll
            for (int mt = 0; mt < 4; mt++)
#pragma unroll
                for (int nt = 0; nt < 4; nt++)
                    mma16816(acc[mt][nt], aF[mt], bF[nt]);
        }
        __syncthreads();
    }

    const int g = lane >> 2, tg2 = (lane & 3) * 2;
#pragma unroll
    for (int nt = 0; nt < 4; nt++) {
        const int col = bn * 128 + wn * 32 + nt * 8 + tg2;
        const float b0 = bias[col], b1 = bias[col + 1];
#pragma unroll
        for (int mt = 0; mt < 4; mt++) {
            const int r0 = bm * 128 + wm * 64 + mt * 16 + g;
            float2 v0 = make_float2(acc[mt][nt][0] + b0, acc[mt][nt][1] + b1);
            float2 v1 = make_float2(acc[mt][nt][2] + b0, acc[mt][nt][3] + b1);
            *(float2*)(C + (size_t)r0 * N + col) = v0;
            *(float2*)(C + (size_t)(r0 + 8) * N + col) = v1;
        }
    }
}

// ---------------------------------------------------------------------------
// RoPE + scatter
// ---------------------------------------------------------------------------
__global__ __launch_bounds__(256) void rope_scatter(
    const float* __restrict__ qkv, float* __restrict__ qout,
    float* __restrict__ cache, const int* __restrict__ offp)
{
    int idx = blockIdx.x * blockDim.x + threadIdx.x;
    int i = idx & 31;
    int h = (idx >> 5) & 15;
    int t = (idx >> 9) & (TT - 1);
    int b = idx >> 20;
    int off = offp ? offp[0] : 0;

    float inv_freq = exp2f(-(float)(2 * i) * (0.015625f * 13.287712379549449f));
    float ang = (float)(t + off) * inv_freq;
    float s, c;
    sincosf(ang, &s, &c);

    size_t base = ((size_t)(b * TT + t)) * D3 + h * HD + 2 * i;
    float q1 = qkv[base], q2 = qkv[base + 1];
    size_t qo = ((size_t)(b * TT + t)) * DD + h * HD + 2 * i;
    qout[qo]     = q1 * c - q2 * s;
    qout[qo + 1] = q1 * s + q2 * c;
    float k1 = qkv[base + DD], k2 = qkv[base + DD + 1];
    size_t ko = ((size_t)((b * 2 + 0) * TT + t)) * DD + h * HD + 2 * i;
    cache[ko]     = k1 * c - k2 * s;
    cache[ko + 1] = k1 * s + k2 * c;
    size_t vo = ((size_t)((b * 2 + 1) * TT + t)) * DD + h * HD + 2 * i;
    cache[vo]     = qkv[base + 2 * DD];
    cache[vo + 1] = qkv[base + 2 * DD + 1];
}

// ---------------------------------------------------------------------------
// Tensor-core flash attention, causal, bf16-split (3-term) for S and PV.
// BM=128 (8 warps x 16 rows), BN=64, hd=64. grid=(8, B*H): CTA px handles
// mblk = px and 15-px (constant work). Smem tiles pitch 72 bf16 (144B rows).
// ---------------------------------------------------------------------------
#define APITCH 72
#define AQSZ (128 * APITCH)          // Q tile bf16 elems
#define AKSZ (64 * APITCH)
#define ATT_SMEM ((2 * AQSZ + 4 * AKSZ) * 2)   // 73728 bytes

__global__ __launch_bounds__(256, 2) void attn_mma(
    const float* __restrict__ q, const float* __restrict__ cache,
    float* __restrict__ ctx)
{
    extern __shared__ __nv_bfloat16 sm16[];
    const uint32_t sbase = smem_u32(sm16);
    const uint32_t sQH = sbase;
    const uint32_t sQL = sQH + AQSZ * 2;
    const uint32_t sKH = sQL + AQSZ * 2;
    const uint32_t sKL = sKH + AKSZ * 2;
    const uint32_t sVH = sKL + AKSZ * 2;
    const uint32_t sVL = sVH + AKSZ * 2;
    __nv_bfloat16* QH = sm16;
    __nv_bfloat16* QL = sm16 + AQSZ;
    __nv_bfloat16* KH = sm16 + 2 * AQSZ;
    __nv_bfloat16* KL = sm16 + 2 * AQSZ + AKSZ;
    __nv_bfloat16* VH = sm16 + 2 * AQSZ + 2 * AKSZ;
    __nv_bfloat16* VL = sm16 + 2 * AQSZ + 3 * AKSZ;

    const int tid = threadIdx.x, wid = tid >> 5, lane = tid & 31;
    const int px = blockIdx.x, bh = blockIdx.y;
    const int b = bh >> 4, h = bh & 15;
    const int l15 = lane & 15, lhi = lane >> 4;
    const int g = lane >> 2, tg2 = (lane & 3) * 2;
    const int b7 = lane & 7, bK = (lane >> 3) & 1;

    const float* qbase = q + ((size_t)(b * TT)) * DD + h * HD;
    const float* kbase = cache + ((size_t)((b * 2 + 0) * TT)) * DD + h * HD;
    const float* vbase = cache + ((size_t)((b * 2 + 1) * TT)) * DD + h * HD;

    for (int pass = 0; pass < 2; pass++) {
        const int mblk = pass ? (15 - px) : px;
        const int NKT = 2 * mblk + 2;

        __syncthreads();   // prior pass fully done with smem
        // Load Q tile 128x64, scale 0.125, split
        {
            const int r = tid >> 1, cg = (tid & 1) * 32;
            const float* src = qbase + (size_t)(mblk * 128 + r) * DD + cg;
#pragma unroll
            for (int u = 0; u < 8; u++) {
                float4 v = *(const float4*)(src + u * 4);
                v.x *= 0.125f; v.y *= 0.125f; v.z *= 0.125f; v.w *= 0.125f;
                __nv_bfloat16 hh[4], ll[4];
                bf16_split(v.x, hh[0], ll[0]);
                bf16_split(v.y, hh[1], ll[1]);
                bf16_split(v.z, hh[2], ll[2]);
                bf16_split(v.w, hh[3], ll[3]);
                *(uint64_t*)&QH[r * APITCH + cg + u * 4] = *(uint64_t*)hh;
                *(uint64_t*)&QL[r * APITCH + cg + u * 4] = *(uint64_t*)ll;
            }
        }

        float o[8][4];
#pragma unroll
        for (int i = 0; i < 8; i++)
#pragma unroll
            for (int j = 0; j < 4; j++) o[i][j] = 0.f;
        float m0 = -1e30f, m1 = -1e30f, l0 = 0.f, l1 = 0.f;

        const int rowA = mblk * 128 + wid * 16 + g;   // j=0,1 row
        const uint32_t aRowOff = (wid * 16 + l15) * (APITCH * 2);

        for (int kb = 0; kb < NKT; kb++) {
            __syncthreads();   // everyone done reading prior K/V
            // Load K,V tile 64x64 fp32 -> split bf16
            {
                const int r = tid >> 2, cg = (tid & 3) * 16;
                const float* ks = kbase + (size_t)(kb * 64 + r) * DD + cg;
                const float* vs = vbase + (size_t)(kb * 64 + r) * DD + cg;
#pragma unroll
                for (int u = 0; u < 4; u++) {
                    float4 v = *(const float4*)(ks + u * 4);
                    __nv_bfloat16 hh[4], ll[4];
                    bf16_split(v.x, hh[0], ll[0]);
                    bf16_split(v.y, hh[1], ll[1]);
                    bf16_split(v.z, hh[2], ll[2]);
                    bf16_split(v.w, hh[3], ll[3]);
                    *(uint64_t*)&KH[r * APITCH + cg + u * 4] = *(uint64_t*)hh;
                    *(uint64_t*)&KL[r * APITCH + cg + u * 4] = *(uint64_t*)ll;
                    float4 w = *(const float4*)(vs + u * 4);
                    bf16_split(w.x, hh[0], ll[0]);
                    bf16_split(w.y, hh[1], ll[1]);
                    bf16_split(w.z, hh[2], ll[2]);
                    bf16_split(w.w, hh[3], ll[3]);
                    *(uint64_t*)&VH[r * APITCH + cg + u * 4] = *(uint64_t*)hh;
                    *(uint64_t*)&VL[r * APITCH + cg + u * 4] = *(uint64_t*)ll;
                }
            }
            __syncthreads();

            // ---- S = Q K^T (3-term split), per warp 16x64 ----
            float s[8][4];
#pragma unroll
            for (int i = 0; i < 8; i++)
#pragma unroll
                for (int j = 0; j < 4; j++) s[i][j] = 0.f;

#pragma unroll
            for (int ks = 0; ks < 4; ks++) {
                const uint32_t ach = (uint32_t)((ks * 2 + lhi) << 4);
                uint32_t aH[4], aL[4];
                ldm_x4(aH, sQH + aRowOff + ach);
                ldm_x4(aL, sQL + aRowOff + ach);
                const uint32_t bch = (uint32_t)((ks * 2 + bK) << 4);
#pragma unroll
                for (int nt = 0; nt < 8; nt++) {
                    const uint32_t bro = (nt * 8 + b7) * (APITCH * 2) + bch;
                    uint32_t bH[2], bL[2];
                    ldm_x2(bH, sKH + bro);
                    ldm_x2(bL, sKL + bro);
                    mma16816(s[nt], aH, bH);
                    mma16816(s[nt], aH, bL);
                    mma16816(s[nt], aL, bH);
                }
            }

            // ---- causal mask (only possible on last two k-tiles) ----
            if (kb >= 2 * mblk) {
                const int cbase = kb * 64;
#pragma unroll
                for (int nt = 0; nt < 8; nt++) {
                    const int c0 = cbase + nt * 8 + tg2;
                    if (c0 > rowA)     s[nt][0] = -1e30f;
                    if (c0 + 1 > rowA) s[nt][1] = -1e30f;
                    if (c0 > rowA + 8)     s[nt][2] = -1e30f;
                    if (c0 + 1 > rowA + 8) s[nt][3] = -1e30f;
                }
            }

            // ---- online softmax (rows g, g+8 of warp tile) ----
            float mx0 = -1e30f, mx1 = -1e30f;
#pragma unroll
            for (int nt = 0; nt < 8; nt++) {
                mx0 = fmaxf(mx0, fmaxf(s[nt][0], s[nt][1]));
                mx1 = fmaxf(mx1, fmaxf(s[nt][2], s[nt][3]));
            }
            mx0 = fmaxf(mx0, __shfl_xor_sync(0xffffffffu, mx0, 1));
            mx0 = fmaxf(mx0, __shfl_xor_sync(0xffffffffu, mx0, 2));
            mx1 = fmaxf(mx1, __shfl_xor_sync(0xffffffffu, mx1, 1));
            mx1 = fmaxf(mx1, __shfl_xor_sync(0xffffffffu, mx1, 2));
            const float mn0 = fmaxf(m0, mx0), mn1 = fmaxf(m1, mx1);
            const float al0 = __expf(m0 - mn0), al1 = __expf(m1 - mn1);
            m0 = mn0; m1 = mn1;
            float sum0 = 0.f, sum1 = 0.f;
#pragma unroll
            for (int nt = 0; nt < 8; nt++) {
                s[nt][0] = __expf(s[nt][0] - mn0);
                s[nt][1] = __expf(s[nt][1] - mn0);
                s[nt][2] = __expf(s[nt][2] - mn1);
                s[nt][3] = __expf(s[nt][3] - mn1);
                sum0 += s[nt][0] + s[nt][1];
                sum1 += s[nt][2] + s[nt][3];
            }
            sum0 += __shfl_xor_sync(0xffffffffu, sum0, 1);
            sum0 += __shfl_xor_sync(0xffffffffu, sum0, 2);
            sum1 += __shfl_xor_sync(0xffffffffu, sum1, 1);
            sum1 += __shfl_xor_sync(0xffffffffu, sum1, 2);
            l0 = l0 * al0 + sum0;
            l1 = l1 * al1 + sum1;
#pragma unroll
            for (int nt = 0; nt < 8; nt++) {
                o[nt][0] *= al0; o[nt][1] *= al0;
                o[nt][2] *= al1; o[nt][3] *= al1;
            }

            // ---- O += P V (P split from regs, V split in smem) ----
#pragma unroll
            for (int kt = 0; kt < 4; kt++) {
                const int n0 = kt * 2, n1 = kt * 2 + 1;
                uint32_t pH[4], pL[4];
                split2(s[n0][0], s[n0][1], pH[0], pL[0]);
                split2(s[n0][2], s[n0][3], pH[1], pL[1]);
                split2(s[n1][0], s[n1][1], pH[2], pL[2]);
                split2(s[n1][2], s[n1][3], pH[3], pL[3]);
                const uint32_t vrow = (kt * 16 + l15) * (APITCH * 2);
#pragma unroll
                for (int nt = 0; nt < 8; nt++) {
                    uint32_t vH[2], vL[2];
                    ldm_x2t(vH, sVH + vrow + nt * 16);
                    ldm_x2t(vL, sVL + vrow + nt * 16);
                    mma16816(o[nt], pH, vH);
                    mma16816(o[nt], pH, vL);
                    mma16816(o[nt], pL, vH);
                }
            }
        }

        // ---- finalize + store ----
        const float inv0 = 1.f / l0, inv1 = 1.f / l1;
        float* crow0 = ctx + (size_t)(b * TT + rowA) * DD + h * HD;
        float* crow1 = crow0 + (size_t)8 * DD;
#pragma unroll
        for (int nt = 0; nt < 8; nt++) {
            *(float2*)(crow0 + nt * 8 + tg2) =
                make_float2(o[nt][0] * inv0, o[nt][1] * inv0);
            *(float2*)(crow1 + nt * 8 + tg2) =
                make_float2(o[nt][2] * inv1, o[nt][3] * inv1);
        }
    }
}

// ---------------------------------------------------------------------------
extern "C" void kernel_launch(void* const* d_in, const int* in_sizes, int n_in,
                              void* d_out, int out_size)
{
    const float* x    = (const float*)d_in[0];
    const float* Wqkv = (const float*)d_in[1];
    const float* bqkv = (const float*)d_in[2];
    const float* Wout = (const float*)d_in[3];
    const float* bout = (const float*)d_in[4];
    const int*   offp = (n_in > 5) ? (const int*)d_in[5] : nullptr;

    float* out   = (float*)d_out;
    float* cache = out + (size_t)BT * DD;

    float *qkv, *qbuf, *ctx;
    __nv_bfloat16 *xh, *xl, *ch, *cl, *wqh, *wql, *woh, *wol;
    cudaGetSymbolAddress((void**)&qkv,  g_qkv);
    cudaGetSymbolAddress((void**)&qbuf, g_q);
    cudaGetSymbolAddress((void**)&ctx,  g_ctx);
    cudaGetSymbolAddress((void**)&xh,   g_x_hi);
    cudaGetSymbolAddress((void**)&xl,   g_x_lo);
    cudaGetSymbolAddress((void**)&ch,   g_c_hi);
    cudaGetSymbolAddress((void**)&cl,   g_c_lo);
    cudaGetSymbolAddress((void**)&wqh,  g_wq_hi);
    cudaGetSymbolAddress((void**)&wql,  g_wq_lo);
    cudaGetSymbolAddress((void**)&woh,  g_wo_hi);
    cudaGetSymbolAddress((void**)&wol,  g_wo_lo);

    cudaFuncSetAttribute(gemm_bf16, cudaFuncAttributeMaxDynamicSharedMemorySize,
                         GSMEM);
    cudaFuncSetAttribute(attn_mma, cudaFuncAttributeMaxDynamicSharedMemorySize,
                         ATT_SMEM);

    // 0) splits
    split_bf16<<<(BT * DD / 4) / 256, 256>>>(x, xh, xl, BT * DD / 4);
    transpose_split<<<dim3(D3 / 32, DD / 32), 256>>>(Wqkv, wqh, wql, DD, D3);
    transpose_split<<<dim3(DD / 32, DD / 32), 256>>>(Wout, woh, wol, DD, DD);

    // 1) QKV projection
    gemm_bf16<<<dim3(D3 / 128, BT / 128), 256, GSMEM>>>(
        xh, xl, wqh, wql, bqkv, qkv, BT, D3, DD);

    // 2) RoPE + scatter
    rope_scatter<<<(BB * TT * NH * 32) / 256, 256>>>(qkv, qbuf, cache, offp);

    // 3) Tensor-core causal flash attention
    attn_mma<<<dim3(8, BB * NH), 256, ATT_SMEM>>>(qbuf, cache, ctx);

    // 4) Output projection
    split_bf16<<<(BT * DD / 4) / 256, 256>>>(ctx, ch, cl, BT * DD / 4);
    gemm_bf16<<<dim3(DD / 128, BT / 128), 256, GSMEM>>>(
        ch, cl, woh, wol, bout, out, BT, DD, DD);
}

// round 11
// speedup vs baseline: 3.0851x; 1.0757x over previous
#include <cuda_runtime.h>
#include <cuda_bf16.h>
#include <math.h>
#include <stdint.h>

#define BB 2
#define TT 2048
#define NH 16
#define HD 64
#define DD 1024
#define D3 3072
#define BT 4096   // BB*TT

// ---------------------------------------------------------------------------
// Scratch (no allocations allowed)
// ---------------------------------------------------------------------------
__device__ float g_qkv[(size_t)BT * D3];
__device__ float g_q  [(size_t)BT * DD];
__device__ __nv_bfloat16 g_x_hi [(size_t)BT * DD];
__device__ __nv_bfloat16 g_x_lo [(size_t)BT * DD];
__device__ __nv_bfloat16 g_c_hi [(size_t)BT * DD];
__device__ __nv_bfloat16 g_c_lo [(size_t)BT * DD];
__device__ __nv_bfloat16 g_wq_hi[(size_t)D3 * DD];   // Wqkv^T
__device__ __nv_bfloat16 g_wq_lo[(size_t)D3 * DD];
__device__ __nv_bfloat16 g_wo_hi[(size_t)DD * DD];   // Wout^T
__device__ __nv_bfloat16 g_wo_lo[(size_t)DD * DD];

// ---------------------------------------------------------------------------
__device__ __forceinline__ uint32_t smem_u32(const void* p) {
    uint32_t a;
    asm("{ .reg .u64 t; cvta.to.shared.u64 t, %1; cvt.u32.u64 %0, t; }"
        : "=r"(a) : "l"(p));
    return a;
}
__device__ __forceinline__ void bf16_split(float v, __nv_bfloat16& h, __nv_bfloat16& l) {
    h = __float2bfloat16_rn(v);
    l = __float2bfloat16_rn(v - __bfloat162float(h));
}
__device__ __forceinline__ void cp16(uint32_t dst, const void* src) {
    asm volatile("cp.async.ca.shared.global [%0], [%1], 16;" :: "r"(dst), "l"(src));
}
__device__ __forceinline__ void cp_commit() {
    asm volatile("cp.async.commit_group;" ::: "memory");
}
__device__ __forceinline__ void cp_wait0() {
    asm volatile("cp.async.wait_group 0;" ::: "memory");
}
__device__ __forceinline__ void cp_wait1() {
    asm volatile("cp.async.wait_group 1;" ::: "memory");
}
__device__ __forceinline__ void ldm_x4(uint32_t* r, uint32_t addr) {
    asm volatile("ldmatrix.sync.aligned.m8n8.x4.shared.b16 {%0,%1,%2,%3}, [%4];"
                 : "=r"(r[0]), "=r"(r[1]), "=r"(r[2]), "=r"(r[3]) : "r"(addr));
}
__device__ __forceinline__ void ldm_x2(uint32_t* r, uint32_t addr) {
    asm volatile("ldmatrix.sync.aligned.m8n8.x2.shared.b16 {%0,%1}, [%2];"
                 : "=r"(r[0]), "=r"(r[1]) : "r"(addr));
}
__device__ __forceinline__ void ldm_x2t(uint32_t* r, uint32_t addr) {
    asm volatile("ldmatrix.sync.aligned.m8n8.x2.trans.shared.b16 {%0,%1}, [%2];"
                 : "=r"(r[0]), "=r"(r[1]) : "r"(addr));
}
__device__ __forceinline__ void mma16816(float* c, const uint32_t* a, const uint32_t* b) {
    asm volatile(
        "mma.sync.aligned.m16n8k16.row.col.f32.bf16.bf16.f32 "
        "{%0,%1,%2,%3}, {%4,%5,%6,%7}, {%8,%9}, {%0,%1,%2,%3};"
        : "+f"(c[0]), "+f"(c[1]), "+f"(c[2]), "+f"(c[3])
        : "r"(a[0]), "r"(a[1]), "r"(a[2]), "r"(a[3]), "r"(b[0]), "r"(b[1]));
}
// pack(lo, hi): low 16 bits = bf16(lo), high = bf16(hi)
__device__ __forceinline__ uint32_t pack_bf16(float lo, float hi) {
    uint32_t r;
    asm("cvt.rn.bf16x2.f32 %0, %1, %2;" : "=r"(r) : "f"(hi), "f"(lo));
    return r;
}
// split pair (a,b) into hi bf16x2 + residual-lo bf16x2 (a in low half)
__device__ __forceinline__ void split2(float a, float b, uint32_t& hi, uint32_t& lo) {
    hi = pack_bf16(a, b);
    float ra = a - __uint_as_float(hi << 16);
    float rb = b - __uint_as_float(hi & 0xffff0000u);
    lo = pack_bf16(ra, rb);
}
// Conflict-free tile offset: 128 rows x 32 k bf16, row pairs packed in 128B
__device__ __forceinline__ uint32_t toff(int row, int c) {
    const int phys = row >> 1;
    const int unit = ((row & 1) * 4 + c) ^ (phys & 3);
    return (uint32_t)(phys * 128 + unit * 16);
}

// ---------------------------------------------------------------------------
// Elementwise fp32 -> bf16 hi/lo split
// ---------------------------------------------------------------------------
__global__ __launch_bounds__(256) void split_bf16(
    const float* __restrict__ src, __nv_bfloat16* __restrict__ hi,
    __nv_bfloat16* __restrict__ lo, int n4)
{
    int i = blockIdx.x * blockDim.x + threadIdx.x;
    if (i >= n4) return;
    float4 v = *(const float4*)(src + (size_t)i * 4);
    __nv_bfloat16 h[4], l[4];
    bf16_split(v.x, h[0], l[0]);
    bf16_split(v.y, h[1], l[1]);
    bf16_split(v.z, h[2], l[2]);
    bf16_split(v.w, h[3], l[3]);
    *(uint64_t*)(hi + (size_t)i * 4) = *(uint64_t*)h;
    *(uint64_t*)(lo + (size_t)i * 4) = *(uint64_t*)l;
}

// ---------------------------------------------------------------------------
// Transpose + bf16 split: W[K][N] -> Thi/Tlo[N][K] bf16
// ---------------------------------------------------------------------------
__global__ __launch_bounds__(256) void transpose_split(
    const float* __restrict__ W, __nv_bfloat16* __restrict__ Thi,
    __nv_bfloat16* __restrict__ Tlo, int K, int N)
{
    __shared__ float t[32][33];
    const int nb = blockIdx.x * 32, kb = blockIdx.y * 32;
    const int tx = threadIdx.x & 31, ty0 = threadIdx.x >> 5;
#pragma unroll
    for (int i = 0; i < 4; i++) {
        int row = ty0 + i * 8;
        t[row][tx] = W[(size_t)(kb + row) * N + nb + tx];
    }
    __syncthreads();
#pragma unroll
    for (int i = 0; i < 4; i++) {
        int row = ty0 + i * 8;
        float v = t[tx][row];
        __nv_bfloat16 h, l;
        bf16_split(v, h, l);
        size_t o = (size_t)(nb + row) * K + kb + tx;
        Thi[o] = h;
        Tlo[o] = l;
    }
}

// ---------------------------------------------------------------------------
// bf16-split GEMM via mma.sync, conflict-free smem layout.
// 128x128 CTA tile, BK=32, double-buffered cp.async. 8 warps, 64x32 warp tile.
// ---------------------------------------------------------------------------
#define GSMEM (2 * 32768)

__global__ __launch_bounds__(256, 2) void gemm_bf16(
    const __nv_bfloat16* __restrict__ Ahi, const __nv_bfloat16* __restrict__ Alo,
    const __nv_bfloat16* __restrict__ Bhi, const __nv_bfloat16* __restrict__ Blo,
    const float* __restrict__ bias, float* __restrict__ C,
    int M, int N, int K)
{
    extern __shared__ char sm[];
    const uint32_t sB = smem_u32(sm);
    const int tid = threadIdx.x, wid = tid >> 5, lane = tid & 31;
    const int bn = blockIdx.x, bm = blockIdx.y;
    const int wm = wid & 1, wn = wid >> 1;
    const int NC = K >> 5;

    const __nv_bfloat16* gbase[4];
    gbase[0] = Ahi + (size_t)bm * 128 * K;
    gbase[1] = Alo + (size_t)bm * 128 * K;
    gbase[2] = Bhi + (size_t)bn * 128 * K;
    gbase[3] = Blo + (size_t)bn * 128 * K;

    auto load_chunk = [&](int c, int s) {
#pragma unroll
        for (int t = 0; t < 8; t++) {
            int id = tid + t * 256;
            int tile = id >> 9;
            int rem = id & 511;
            int row = rem >> 2, ch = rem & 3;
            const __nv_bfloat16* src = gbase[tile] + (size_t)row * K + c * 32 + ch * 8;
            uint32_t dst = sB + s * 32768 + tile * 8192 + toff(row, ch);
            cp16(dst, src);
        }
    };

    float acc[4][4][4];
#pragma unroll
    for (int i = 0; i < 4; i++)
#pragma unroll
        for (int j = 0; j < 4; j++)
#pragma unroll
            for (int k = 0; k < 4; k++) acc[i][j][k] = 0.f;

    const int l15 = lane & 15, lhi = lane >> 4;
    const int b7 = lane & 7, bK = (lane >> 3) & 1;

    load_chunk(0, 0);
    cp_commit();

    for (int c = 0; c < NC; c++) {
        const int s = c & 1;
        if (c + 1 < NC) {
            load_chunk(c + 1, s ^ 1);
            cp_commit();
            cp_wait1();
        } else {
            cp_wait0();
        }
        __syncthreads();

        const uint32_t base = sB + s * 32768;
        const uint32_t aHiT = base, aLoT = base + 8192;
        const uint32_t bHiT = base + 16384, bLoT = base + 24576;

#pragma unroll
        for (int ks = 0; ks < 2; ks++) {
            const int ks2 = ks * 2;
            uint32_t aOff[4], bOff[4];
#pragma unroll
            for (int mt = 0; mt < 4; mt++)
                aOff[mt] = toff(wm * 64 + mt * 16 + l15, ks2 + lhi);
#pragma unroll
            for (int nt = 0; nt < 4; nt++)
                bOff[nt] = toff(wn * 32 + nt * 8 + b7, ks2 + bK);

            uint32_t aF[4][4], bF[4][2], bF2[4][2];
#pragma unroll
            for (int mt = 0; mt < 4; mt++) ldm_x4(aF[mt], aHiT + aOff[mt]);
#pragma unroll
            for (int nt = 0; nt < 4; nt++) ldm_x2(bF[nt], bHiT + bOff[nt]);
#pragma unroll
            for (int mt = 0; mt < 4; mt++)
#pragma unroll
                for (int nt = 0; nt < 4; nt++)
                    mma16816(acc[mt][nt], aF[mt], bF[nt]);
#pragma unroll
            for (int nt = 0; nt < 4; nt++) ldm_x2(bF2[nt], bLoT + bOff[nt]);
#pragma unroll
            for (int mt = 0; mt < 4; mt++)
#pragma unroll
                for (int nt = 0; nt < 4; nt++)
                    mma16816(acc[mt][nt], aF[mt], bF2[nt]);
#pragma unroll
            for (int mt = 0; mt < 4; mt++) ldm_x4(aF[mt], aLoT + aOff[mt]);
#pragma unroll
            for (int mt = 0; mt < 4; mt++)
#pragma unroll
                for (int nt = 0; nt < 4; nt++)
                    mma16816(acc[mt][nt], aF[mt], bF[nt]);
        }
        __syncthreads();
    }

    const int g = lane >> 2, tg2 = (lane & 3) * 2;
#pragma unroll
    for (int nt = 0; nt < 4; nt++) {
        const int col = bn * 128 + wn * 32 + nt * 8 + tg2;
        const float b0 = bias[col], b1 = bias[col + 1];
#pragma unroll
        for (int mt = 0; mt < 4; mt++) {
            const int r0 = bm * 128 + wm * 64 + mt * 16 + g;
            float2 v0 = make_float2(acc[mt][nt][0] + b0, acc[mt][nt][1] + b1);
            float2 v1 = make_float2(acc[mt][nt][2] + b0, acc[mt][nt][3] + b1);
            *(float2*)(C + (size_t)r0 * N + col) = v0;
            *(float2*)(C + (size_t)(r0 + 8) * N + col) = v1;
        }
    }
}

// ---------------------------------------------------------------------------
// RoPE + scatter
// ---------------------------------------------------------------------------
__global__ __launch_bounds__(256) void rope_scatter(
    const float* __restrict__ qkv, float* __restrict__ qout,
    float* __restrict__ cache, const int* __restrict__ offp)
{
    int idx = blockIdx.x * blockDim.x + threadIdx.x;
    int i = idx & 31;
    int h = (idx >> 5) & 15;
    int t = (idx >> 9) & (TT - 1);
    int b = idx >> 20;
    int off = offp ? offp[0] : 0;

    float inv_freq = exp2f(-(float)(2 * i) * (0.015625f * 13.287712379549449f));
    float ang = (float)(t + off) * inv_freq;
    float s, c;
    sincosf(ang, &s, &c);

    size_t base = ((size_t)(b * TT + t)) * D3 + h * HD + 2 * i;
    float q1 = qkv[base], q2 = qkv[base + 1];
    size_t qo = ((size_t)(b * TT + t)) * DD + h * HD + 2 * i;
    qout[qo]     = q1 * c - q2 * s;
    qout[qo + 1] = q1 * s + q2 * c;
    float k1 = qkv[base + DD], k2 = qkv[base + DD + 1];
    size_t ko = ((size_t)((b * 2 + 0) * TT + t)) * DD + h * HD + 2 * i;
    cache[ko]     = k1 * c - k2 * s;
    cache[ko + 1] = k1 * s + k2 * c;
    size_t vo = ((size_t)((b * 2 + 1) * TT + t)) * DD + h * HD + 2 * i;
    cache[vo]     = qkv[base + 2 * DD];
    cache[vo + 1] = qkv[base + 2 * DD + 1];
}

// ---------------------------------------------------------------------------
// Tensor-core flash attention, causal, bf16-split (3-term) for S and PV.
// BM=128 (8 warps x 16 rows), BN=64, hd=64. grid=(8, B*H): CTA px handles
// mblk = px and 15-px. Smem tiles pitch 72 bf16 (conflict-free).
// Epilogue writes ctx directly as bf16 hi/lo (fused split).
// ---------------------------------------------------------------------------
#define APITCH 72
#define AQSZ (128 * APITCH)
#define AKSZ (64 * APITCH)
#define ATT_SMEM ((2 * AQSZ + 4 * AKSZ) * 2)   // 73728 bytes

__global__ __launch_bounds__(256, 2) void attn_mma(
    const float* __restrict__ q, const float* __restrict__ cache,
    __nv_bfloat16* __restrict__ ch, __nv_bfloat16* __restrict__ cl)
{
    extern __shared__ __nv_bfloat16 sm16[];
    const uint32_t sbase = smem_u32(sm16);
    const uint32_t sQH = sbase;
    const uint32_t sQL = sQH + AQSZ * 2;
    const uint32_t sKH = sQL + AQSZ * 2;
    const uint32_t sKL = sKH + AKSZ * 2;
    const uint32_t sVH = sKL + AKSZ * 2;
    const uint32_t sVL = sVH + AKSZ * 2;
    __nv_bfloat16* QH = sm16;
    __nv_bfloat16* QL = sm16 + AQSZ;
    __nv_bfloat16* KH = sm16 + 2 * AQSZ;
    __nv_bfloat16* KL = sm16 + 2 * AQSZ + AKSZ;
    __nv_bfloat16* VH = sm16 + 2 * AQSZ + 2 * AKSZ;
    __nv_bfloat16* VL = sm16 + 2 * AQSZ + 3 * AKSZ;

    const int tid = threadIdx.x, wid = tid >> 5, lane = tid & 31;
    const int px = blockIdx.x, bh = blockIdx.y;
    const int b = bh >> 4, h = bh & 15;
    const int l15 = lane & 15, lhi = lane >> 4;
    const int g = lane >> 2, tg2 = (lane & 3) * 2;
    const int b7 = lane & 7, bK = (lane >> 3) & 1;

    const float* qbase = q + ((size_t)(b * TT)) * DD + h * HD;
    const float* kbase = cache + ((size_t)((b * 2 + 0) * TT)) * DD + h * HD;
    const float* vbase = cache + ((size_t)((b * 2 + 1) * TT)) * DD + h * HD;

    for (int pass = 0; pass < 2; pass++) {
        const int mblk = pass ? (15 - px) : px;
        const int NKT = 2 * mblk + 2;

        __syncthreads();
        {
            const int r = tid >> 1, cg = (tid & 1) * 32;
            const float* src = qbase + (size_t)(mblk * 128 + r) * DD + cg;
#pragma unroll
            for (int u = 0; u < 8; u++) {
                float4 v = *(const float4*)(src + u * 4);
                v.x *= 0.125f; v.y *= 0.125f; v.z *= 0.125f; v.w *= 0.125f;
                __nv_bfloat16 hh[4], ll[4];
                bf16_split(v.x, hh[0], ll[0]);
                bf16_split(v.y, hh[1], ll[1]);
                bf16_split(v.z, hh[2], ll[2]);
                bf16_split(v.w, hh[3], ll[3]);
                *(uint64_t*)&QH[r * APITCH + cg + u * 4] = *(uint64_t*)hh;
                *(uint64_t*)&QL[r * APITCH + cg + u * 4] = *(uint64_t*)ll;
            }
        }

        float o[8][4];
#pragma unroll
        for (int i = 0; i < 8; i++)
#pragma unroll
            for (int j = 0; j < 4; j++) o[i][j] = 0.f;
        float m0 = -1e30f, m1 = -1e30f, l0 = 0.f, l1 = 0.f;

        const int rowA = mblk * 128 + wid * 16 + g;
        const uint32_t aRowOff = (wid * 16 + l15) * (APITCH * 2);

        for (int kb = 0; kb < NKT; kb++) {
            __syncthreads();
            {
                const int r = tid >> 2, cg = (tid & 3) * 16;
                const float* ks = kbase + (size_t)(kb * 64 + r) * DD + cg;
                const float* vs = vbase + (size_t)(kb * 64 + r) * DD + cg;
#pragma unroll
                for (int u = 0; u < 4; u++) {
                    float4 v = *(const float4*)(ks + u * 4);
                    __nv_bfloat16 hh[4], ll[4];
                    bf16_split(v.x, hh[0], ll[0]);
                    bf16_split(v.y, hh[1], ll[1]);
                    bf16_split(v.z, hh[2], ll[2]);
                    bf16_split(v.w, hh[3], ll[3]);
                    *(uint64_t*)&KH[r * APITCH + cg + u * 4] = *(uint64_t*)hh;
                    *(uint64_t*)&KL[r * APITCH + cg + u * 4] = *(uint64_t*)ll;
                    float4 w = *(const float4*)(vs + u * 4);
                    bf16_split(w.x, hh[0], ll[0]);
                    bf16_split(w.y, hh[1], ll[1]);
                    bf16_split(w.z, hh[2], ll[2]);
                    bf16_split(w.w, hh[3], ll[3]);
                    *(uint64_t*)&VH[r * APITCH + cg + u * 4] = *(uint64_t*)hh;
                    *(uint64_t*)&VL[r * APITCH + cg + u * 4] = *(uint64_t*)ll;
                }
            }
            __syncthreads();

            float s[8][4];
#pragma unroll
            for (int i = 0; i < 8; i++)
#pragma unroll
                for (int j = 0; j < 4; j++) s[i][j] = 0.f;

#pragma unroll
            for (int ks = 0; ks < 4; ks++) {
                const uint32_t ach = (uint32_t)((ks * 2 + lhi) << 4);
                uint32_t aH[4], aL[4];
                ldm_x4(aH, sQH + aRowOff + ach);
                ldm_x4(aL, sQL + aRowOff + ach);
                const uint32_t bch = (uint32_t)((ks * 2 + bK) << 4);
#pragma unroll
                for (int nt = 0; nt < 8; nt++) {
                    const uint32_t bro = (nt * 8 + b7) * (APITCH * 2) + bch;
                    uint32_t bH[2], bL[2];
                    ldm_x2(bH, sKH + bro);
                    ldm_x2(bL, sKL + bro);
                    mma16816(s[nt], aH, bH);
                    mma16816(s[nt], aH, bL);
                    mma16816(s[nt], aL, bH);
                }
            }

            if (kb >= 2 * mblk) {
                const int cbase = kb * 64;
#pragma unroll
                for (int nt = 0; nt < 8; nt++) {
                    const int c0 = cbase + nt * 8 + tg2;
                    if (c0 > rowA)     s[nt][0] = -1e30f;
                    if (c0 + 1 > rowA) s[nt][1] = -1e30f;
                    if (c0 > rowA + 8)     s[nt][2] = -1e30f;
                    if (c0 + 1 > rowA + 8) s[nt][3] = -1e30f;
                }
            }

            float mx0 = -1e30f, mx1 = -1e30f;
#pragma unroll
            for (int nt = 0; nt < 8; nt++) {
                mx0 = fmaxf(mx0, fmaxf(s[nt][0], s[nt][1]));
                mx1 = fmaxf(mx1, fmaxf(s[nt][2], s[nt][3]));
            }
            mx0 = fmaxf(mx0, __shfl_xor_sync(0xffffffffu, mx0, 1));
            mx0 = fmaxf(mx0, __shfl_xor_sync(0xffffffffu, mx0, 2));
            mx1 = fmaxf(mx1, __shfl_xor_sync(0xffffffffu, mx1, 1));
            mx1 = fmaxf(mx1, __shfl_xor_sync(0xffffffffu, mx1, 2));
            const float mn0 = fmaxf(m0, mx0), mn1 = fmaxf(m1, mx1);
            const float al0 = __expf(m0 - mn0), al1 = __expf(m1 - mn1);
            m0 = mn0; m1 = mn1;
            float sum0 = 0.f, sum1 = 0.f;
#pragma unroll
            for (int nt = 0; nt < 8; nt++) {
                s[nt][0] = __expf(s[nt][0] - mn0);
                s[nt][1] = __expf(s[nt][1] - mn0);
                s[nt][2] = __expf(s[nt][2] - mn1);
                s[nt][3] = __expf(s[nt][3] - mn1);
                sum0 += s[nt][0] + s[nt][1];
                sum1 += s[nt][2] + s[nt][3];
            }
            sum0 += __shfl_xor_sync(0xffffffffu, sum0, 1);
            sum0 += __shfl_xor_sync(0xffffffffu, sum0, 2);
            sum1 += __shfl_xor_sync(0xffffffffu, sum1, 1);
            sum1 += __shfl_xor_sync(0xffffffffu, sum1, 2);
            l0 = l0 * al0 + sum0;
            l1 = l1 * al1 + sum1;
#pragma unroll
            for (int nt = 0; nt < 8; nt++) {
                o[nt][0] *= al0; o[nt][1] *= al0;
                o[nt][2] *= al1; o[nt][3] *= al1;
            }

#pragma unroll
            for (int kt = 0; kt < 4; kt++) {
                const int n0 = kt * 2, n1 = kt * 2 + 1;
                uint32_t pH[4], pL[4];
                split2(s[n0][0], s[n0][1], pH[0], pL[0]);
                split2(s[n0][2], s[n0][3], pH[1], pL[1]);
                split2(s[n1][0], s[n1][1], pH[2], pL[2]);
                split2(s[n1][2], s[n1][3], pH[3], pL[3]);
                const uint32_t vrow = (kt * 16 + l15) * (APITCH * 2);
#pragma unroll
                for (int nt = 0; nt < 8; nt++) {
                    uint32_t vH[2], vL[2];
                    ldm_x2t(vH, sVH + vrow + nt * 16);
                    ldm_x2t(vL, sVL + vrow + nt * 16);
                    mma16816(o[nt], pH, vH);
                    mma16816(o[nt], pH, vL);
                    mma16816(o[nt], pL, vH);
                }
            }
        }

        // ---- finalize + fused bf16 hi/lo store ----
        const float inv0 = 1.f / l0, inv1 = 1.f / l1;
        __nv_bfloat16* ch0 = ch + (size_t)(b * TT + rowA) * DD + h * HD;
        __nv_bfloat16* cl0 = cl + (size_t)(b * TT + rowA) * DD + h * HD;
        __nv_bfloat16* ch1 = ch0 + (size_t)8 * DD;
        __nv_bfloat16* cl1 = cl0 + (size_t)8 * DD;
#pragma unroll
        for (int nt = 0; nt < 8; nt++) {
            uint32_t hi, lo;
            split2(o[nt][0] * inv0, o[nt][1] * inv0, hi, lo);
            *(uint32_t*)(ch0 + nt * 8 + tg2) = hi;
            *(uint32_t*)(cl0 + nt * 8 + tg2) = lo;
            split2(o[nt][2] * inv1, o[nt][3] * inv1, hi, lo);
            *(uint32_t*)(ch1 + nt * 8 + tg2) = hi;
            *(uint32_t*)(cl1 + nt * 8 + tg2) = lo;
        }
    }
}

// ---------------------------------------------------------------------------
extern "C" void kernel_launch(void* const* d_in, const int* in_sizes, int n_in,
                              void* d_out, int out_size)
{
    const float* x    = (const float*)d_in[0];
    const float* Wqkv = (const float*)d_in[1];
    const float* bqkv = (const float*)d_in[2];
    const float* Wout = (const float*)d_in[3];
    const float* bout = (const float*)d_in[4];
    const int*   offp = (n_in > 5) ? (const int*)d_in[5] : nullptr;

    float* out   = (float*)d_out;
    float* cache = out + (size_t)BT * DD;

    float *qkv, *qbuf;
    __nv_bfloat16 *xh, *xl, *ch, *cl, *wqh, *wql, *woh, *wol;
    cudaGetSymbolAddress((void**)&qkv,  g_qkv);
    cudaGetSymbolAddress((void**)&qbuf, g_q);
    cudaGetSymbolAddress((void**)&xh,   g_x_hi);
    cudaGetSymbolAddress((void**)&xl,   g_x_lo);
    cudaGetSymbolAddress((void**)&ch,   g_c_hi);
    cudaGetSymbolAddress((void**)&cl,   g_c_lo);
    cudaGetSymbolAddress((void**)&wqh,  g_wq_hi);
    cudaGetSymbolAddress((void**)&wql,  g_wq_lo);
    cudaGetSymbolAddress((void**)&woh,  g_wo_hi);
    cudaGetSymbolAddress((void**)&wol,  g_wo_lo);

    cudaFuncSetAttribute(gemm_bf16, cudaFuncAttributeMaxDynamicSharedMemorySize,
                         GSMEM);
    cudaFuncSetAttribute(attn_mma, cudaFuncAttributeMaxDynamicSharedMemorySize,
                         ATT_SMEM);

    // 0) splits
    split_bf16<<<(BT * DD / 4) / 256, 256>>>(x, xh, xl, BT * DD / 4);
    transpose_split<<<dim3(D3 / 32, DD / 32), 256>>>(Wqkv, wqh, wql, DD, D3);
    transpose_split<<<dim3(DD / 32, DD / 32), 256>>>(Wout, woh, wol, DD, DD);

    // 1) QKV projection
    gemm_bf16<<<dim3(D3 / 128, BT / 128), 256, GSMEM>>>(
        xh, xl, wqh, wql, bqkv, qkv, BT, D3, DD);

    // 2) RoPE + scatter
    rope_scatter<<<(BB * TT * NH * 32) / 256, 256>>>(qkv, qbuf, cache, offp);

    // 3) Tensor-core causal flash attention (writes ctx as bf16 hi/lo)
    attn_mma<<<dim3(8, BB * NH), 256, ATT_SMEM>>>(qbuf, cache, ch, cl);

    // 4) Output projection
    gemm_bf16<<<dim3(DD / 128, BT / 128), 256, GSMEM>>>(
        ch, cl, woh, wol, bout, out, BT, DD, DD);
}